// round 9
// baseline (speedup 1.0000x reference)
#include <cuda_runtime.h>
#include <cuda_fp16.h>

#define N_NODES 12288
#define DIM 64
#define N_EDGES 262144
#define EPS_F 0.01f

// Repacked storage: r rows compressed to fp16 (64 halfs = 128B = ONE cache
// line per row), m kept fp32.
__device__ __half g_rh[N_NODES * DIM];
__device__ float  g_m[N_NODES];

// Pre-pass, 4 elements per thread: 4 independent coalesced LDG.32 (MLP=4)
// + one vectorized 8-byte store of 4 halfs. 196608 threads total.
__global__ void __launch_bounds__(256) repack_kernel(const float* __restrict__ z) {
    int t = blockIdx.x * blockDim.x + threadIdx.x;
    const int quads = N_NODES * DIM / 4;   // 196608
    if (t < quads) {
        int row = t >> 4;          // 16 quads per 64-wide row
        int col = (t & 15) << 2;
        const float* src = z + row * 65 + col;
        float x0 = src[0];
        float x1 = src[1];
        float x2 = src[2];
        float x3 = src[3];
        __half2 h0 = __floats2half2_rn(x0, x1);
        __half2 h1 = __floats2half2_rn(x2, x3);
        uint2 w;
        w.x = *reinterpret_cast<unsigned*>(&h0);
        w.y = *reinterpret_cast<unsigned*>(&h1);
        *reinterpret_cast<uint2*>(g_rh + (size_t)t * 4) = w;
    }
    if (t < N_NODES) {
        g_m[t] = z[t * 65 + 64];
    }
}

// 8 lanes per group, 2 edges per thread. fp16 rows: one LDG.128 wavefront
// per row. Inner loop subtracts in half2 (HSUB2) and converts only the
// DIFFERENCE to fp32 (2 F2F instead of 4) before the FMA -> 5 instr per
// half2-pair instead of 8.
__global__ void __launch_bounds__(256) edge_kernel(
        const int* __restrict__ eidx,
        const float* __restrict__ lptr,
        float4* __restrict__ out) {
    unsigned tid = blockIdx.x * blockDim.x + threadIdx.x;
    unsigned g = tid >> 3;            // group id: handles edges 2g, 2g+1
    unsigned i = tid & 7u;
    unsigned e0 = 2u * g;
    if (e0 >= N_EDGES) return;
    unsigned e1 = e0 + 1u;

    int u0 = eidx[e0];
    int v0 = eidx[N_EDGES + e0];
    int u1 = eidx[e1];
    int v1 = eidx[N_EDGES + e1];

    const uint4* __restrict__ rb = reinterpret_cast<const uint4*>(g_rh);

    // Front-load all payload (4 independent LDG.128, one per row) + m.
    uint4 pa0 = rb[u0 * 8 + i];   // 8 halfs of row u0
    uint4 pb0 = rb[v0 * 8 + i];
    uint4 pa1 = rb[u1 * 8 + i];
    uint4 pb1 = rb[v1 * 8 + i];
    float m_u0 = g_m[u0];
    float m_v0 = g_m[v0];
    float m_u1 = g_m[u1];
    float m_v1 = g_m[v1];

    const __half2* ha0 = reinterpret_cast<const __half2*>(&pa0);
    const __half2* hb0 = reinterpret_cast<const __half2*>(&pb0);
    const __half2* ha1 = reinterpret_cast<const __half2*>(&pa1);
    const __half2* hb1 = reinterpret_cast<const __half2*>(&pb1);

    float acc0 = 0.0f, acc1 = 0.0f;
    #pragma unroll
    for (int k = 0; k < 4; k++) {
        __half2 d0 = __hsub2(ha0[k], hb0[k]);
        __half2 d1 = __hsub2(ha1[k], hb1[k]);
        float2 f0 = __half22float2(d0);
        float2 f1 = __half22float2(d1);
        acc0 = fmaf(f0.x, f0.x, acc0);
        acc0 = fmaf(f0.y, f0.y, acc0);
        acc1 = fmaf(f1.x, f1.x, acc1);
        acc1 = fmaf(f1.y, f1.y, acc1);
    }

    // Interleaved 3-step reduces across the 8-lane group.
    acc0 += __shfl_xor_sync(0xffffffffu, acc0, 4);
    acc1 += __shfl_xor_sync(0xffffffffu, acc1, 4);
    acc0 += __shfl_xor_sync(0xffffffffu, acc0, 2);
    acc1 += __shfl_xor_sync(0xffffffffu, acc1, 2);
    acc0 += __shfl_xor_sync(0xffffffffu, acc0, 1);
    acc1 += __shfl_xor_sync(0xffffffffu, acc1, 1);

    if (i == 0) {
        float l   = __ldg(lptr);
        float lg0 = __logf(acc0 + EPS_F);
        float lg1 = __logf(acc1 + EPS_F);

        float luv0 = fmaf(-l, lg0, m_v0);
        float lvu0 = fmaf(-l, lg0, m_u0);
        float luv1 = fmaf(-l, lg1, m_v1);
        float lvu1 = fmaf(-l, lg1, m_u1);

        float suv0 = __fdividef(1.0f, 1.0f + __expf(-luv0));
        float svu0 = __fdividef(1.0f, 1.0f + __expf(-lvu0));
        float suv1 = __fdividef(1.0f, 1.0f + __expf(-luv1));
        float svu1 = __fdividef(1.0f, 1.0f + __expf(-lvu1));

        float4 o0, o1;
        o0.x = (1.0f - suv0) * (1.0f - svu0);
        o0.y = suv0 * (1.0f - svu0);
        o0.z = suv0 * svu0;
        o0.w = (1.0f - suv0) * svu0;
        o1.x = (1.0f - suv1) * (1.0f - svu1);
        o1.y = suv1 * (1.0f - svu1);
        o1.z = suv1 * svu1;
        o1.w = (1.0f - suv1) * svu1;
        out[e0] = o0;
        out[e1] = o1;
    }
}

extern "C" void kernel_launch(void* const* d_in, const int* in_sizes, int n_in,
                              void* d_out, int out_size) {
    const float* z    = (const float*)d_in[0];
    const float* l    = (const float*)d_in[1];
    const int*   eidx = (const int*)d_in[2];   // int64 in reference, but JAX
                                               // x64 is disabled -> int32
    float4*      out  = (float4*)d_out;

    // Repack: 196608 threads (4 elements each)
    {
        int threads = 256;
        int quads = N_NODES * DIM / 4;
        int blocks = (quads + threads - 1) / threads;
        repack_kernel<<<blocks, threads>>>(z);
    }

    // Edge kernel: 8 threads per 2 edges -> N_EDGES*4 = 1,048,576 threads
    {
        int threads = 256;
        long long total = (long long)N_EDGES * 4;
        int blocks = (int)((total + threads - 1) / threads);
        edge_kernel<<<blocks, threads>>>(eidx, l, out);
    }
}

// round 10
// speedup vs baseline: 1.2780x; 1.2780x over previous
#include <cuda_runtime.h>
#include <cuda_fp16.h>

#define N_NODES 12288
#define DIM 64
#define N_EDGES 262144
#define EPS_F 0.01f

// Repacked storage: r rows compressed to fp16 (64 halfs = 128B = ONE cache
// line per row), m kept fp32.
__device__ __half g_rh[N_NODES * DIM];
__device__ float  g_m[N_NODES];

// Pre-pass, 4 elements per thread: 4 independent coalesced LDG.32 (MLP=4)
// + one vectorized 8-byte store of 4 halfs. 196608 threads total.
__global__ void __launch_bounds__(256) repack_kernel(const float* __restrict__ z) {
    int t = blockIdx.x * blockDim.x + threadIdx.x;
    const int quads = N_NODES * DIM / 4;   // 196608
    if (t < quads) {
        int row = t >> 4;          // 16 quads per 64-wide row
        int col = (t & 15) << 2;
        const float* src = z + row * 65 + col;
        float x0 = src[0];
        float x1 = src[1];
        float x2 = src[2];
        float x3 = src[3];
        __half2 h0 = __floats2half2_rn(x0, x1);
        __half2 h1 = __floats2half2_rn(x2, x3);
        uint2 w;
        w.x = *reinterpret_cast<unsigned*>(&h0);
        w.y = *reinterpret_cast<unsigned*>(&h1);
        *reinterpret_cast<uint2*>(g_rh + (size_t)t * 4) = w;
    }
    if (t < N_NODES) {
        g_m[t] = z[t * 65 + 64];
    }
}

// Accumulate ||a-b||^2 contribution of one 16B chunk (8 halfs), fp32 math
// (the proven R8 inner-loop form: convert both operands, subtract in fp32).
__device__ __forceinline__ float sq_chunk(const uint4& pa, const uint4& pb) {
    const __half2* ha = reinterpret_cast<const __half2*>(&pa);
    const __half2* hb = reinterpret_cast<const __half2*>(&pb);
    float acc = 0.0f;
    #pragma unroll
    for (int k = 0; k < 4; k++) {
        float2 fa = __half22float2(ha[k]);
        float2 fb = __half22float2(hb[k]);
        float dx = fa.x - fb.x;
        float dy = fa.y - fb.y;
        acc = fmaf(dx, dx, acc);
        acc = fmaf(dy, dy, acc);
    }
    return acc;
}

__device__ __forceinline__ void tail2(unsigned i, unsigned e, float l,
                                      float acc0, float acc1,
                                      float m_u0, float m_v0,
                                      float m_u1, float m_v1,
                                      float4* __restrict__ out) {
    // 3-step interleaved reduce across the 8-lane group.
    acc0 += __shfl_xor_sync(0xffffffffu, acc0, 4);
    acc1 += __shfl_xor_sync(0xffffffffu, acc1, 4);
    acc0 += __shfl_xor_sync(0xffffffffu, acc0, 2);
    acc1 += __shfl_xor_sync(0xffffffffu, acc1, 2);
    acc0 += __shfl_xor_sync(0xffffffffu, acc0, 1);
    acc1 += __shfl_xor_sync(0xffffffffu, acc1, 1);

    if (i == 0) {
        float lg0 = __logf(acc0 + EPS_F);
        float lg1 = __logf(acc1 + EPS_F);
        float luv0 = fmaf(-l, lg0, m_v0);
        float lvu0 = fmaf(-l, lg0, m_u0);
        float luv1 = fmaf(-l, lg1, m_v1);
        float lvu1 = fmaf(-l, lg1, m_u1);
        float suv0 = __fdividef(1.0f, 1.0f + __expf(-luv0));
        float svu0 = __fdividef(1.0f, 1.0f + __expf(-lvu0));
        float suv1 = __fdividef(1.0f, 1.0f + __expf(-luv1));
        float svu1 = __fdividef(1.0f, 1.0f + __expf(-lvu1));
        float4 o0, o1;
        o0.x = (1.0f - suv0) * (1.0f - svu0);
        o0.y = suv0 * (1.0f - svu0);
        o0.z = suv0 * svu0;
        o0.w = (1.0f - suv0) * svu0;
        o1.x = (1.0f - suv1) * (1.0f - svu1);
        o1.y = suv1 * (1.0f - svu1);
        o1.z = suv1 * svu1;
        o1.w = (1.0f - suv1) * svu1;
        out[e]     = o0;
        out[e + 1] = o1;
    }
}

// 8 lanes per group, 4 edges per group as two software-pipelined pairs.
// fp16 rows (one LDG.128 wavefront per row) keep payload registers at 16
// per pair, so the pipelined 4-edge structure stays under ~48 regs and
// occupancy remains high while doubling loads-in-flight per thread.
__global__ void __launch_bounds__(256) edge_kernel(
        const int* __restrict__ eidx,
        const float* __restrict__ lptr,
        float4* __restrict__ out) {
    unsigned tid = blockIdx.x * blockDim.x + threadIdx.x;
    unsigned g = tid >> 3;           // group: edges 4g..4g+3
    unsigned i = tid & 7u;
    unsigned e = g * 4u;
    if (e >= N_EDGES) return;

    // All indices up front (coalesced).
    int u0 = eidx[e];
    int v0 = eidx[N_EDGES + e];
    int u1 = eidx[e + 1];
    int v1 = eidx[N_EDGES + e + 1];
    int u2 = eidx[e + 2];
    int v2 = eidx[N_EDGES + e + 2];
    int u3 = eidx[e + 3];
    int v3 = eidx[N_EDGES + e + 3];

    const uint4* __restrict__ rb = reinterpret_cast<const uint4*>(g_rh);
    float l = __ldg(lptr);

    // ---- pair 0 payload + m ----
    uint4 pa0 = rb[u0 * 8 + i];
    uint4 pb0 = rb[v0 * 8 + i];
    uint4 pa1 = rb[u1 * 8 + i];
    uint4 pb1 = rb[v1 * 8 + i];
    float m_u0 = g_m[u0];
    float m_v0 = g_m[v0];
    float m_u1 = g_m[u1];
    float m_v1 = g_m[v1];

    // ---- pair 0 accumulate (payload regs die here) ----
    float acc0 = sq_chunk(pa0, pb0);
    float acc1 = sq_chunk(pa1, pb1);

    // ---- pair 1 payload + m: in flight during pair-0 reduce/tail ----
    uint4 pa2 = rb[u2 * 8 + i];
    uint4 pb2 = rb[v2 * 8 + i];
    uint4 pa3 = rb[u3 * 8 + i];
    uint4 pb3 = rb[v3 * 8 + i];
    float m_u2 = g_m[u2];
    float m_v2 = g_m[v2];
    float m_u3 = g_m[u3];
    float m_v3 = g_m[v3];

    // ---- pair 0 reduce + tail + store (covers pair-1 latency) ----
    tail2(i, e, l, acc0, acc1, m_u0, m_v0, m_u1, m_v1, out);

    // ---- pair 1 ----
    float acc2 = sq_chunk(pa2, pb2);
    float acc3 = sq_chunk(pa3, pb3);
    tail2(i, e + 2, l, acc2, acc3, m_u2, m_v2, m_u3, m_v3, out);
}

extern "C" void kernel_launch(void* const* d_in, const int* in_sizes, int n_in,
                              void* d_out, int out_size) {
    const float* z    = (const float*)d_in[0];
    const float* l    = (const float*)d_in[1];
    const int*   eidx = (const int*)d_in[2];   // int64 in reference, but JAX
                                               // x64 is disabled -> int32
    float4*      out  = (float4*)d_out;

    // Repack: 196608 threads (4 elements each)
    {
        int threads = 256;
        int quads = N_NODES * DIM / 4;
        int blocks = (quads + threads - 1) / threads;
        repack_kernel<<<blocks, threads>>>(z);
    }

    // Edge kernel: 8 threads per 4 edges -> N_EDGES*2 = 524288 threads
    {
        int threads = 256;
        long long total = (long long)N_EDGES * 2;
        int blocks = (int)((total + threads - 1) / threads);
        edge_kernel<<<blocks, threads>>>(eidx, l, out);
    }
}